// round 2
// baseline (speedup 1.0000x reference)
#include <cuda_runtime.h>
#include <math.h>

#define B_  8
#define N_  2048
#define C_  1024
#define H_  16
#define D_  64
#define M_  (B_*N_)   // 16384
#define LN10000 9.210340371976184f

// Scratch (device globals: allocation-free contract)
__device__ float g_q[M_*C_];      // gelu(q)+0.21, pre-rope
__device__ float g_k[M_*C_];     // rope(gelu(k)+0.21)
__device__ float g_v[M_*C_];
__device__ float g_attn[M_*C_];
__device__ float g_ksum[B_*C_];  // sum over n of gelu(k)+0.21 (pre-rope)
__device__ float g_kv[B_*H_*D_*D_];

__device__ __forceinline__ float gelu_exact(float x){
    return 0.5f*x*(1.0f+erff(x*0.70710678118654752f));
}

__global__ void zero_ksum_kernel(){
    int i = blockIdx.x*blockDim.x + threadIdx.x;
    if (i < B_*C_) g_ksum[i] = 0.f;
}

// ---------------------------------------------------------------------------
// GEMM: OUT[m, c] = sum_k X[m,k]*W[c,k] + bias[c]
// w=0 -> q: gelu+0.21                    -> g_q
// w=1 -> k: gelu+0.21, rope, ksum atomic -> g_k (+ g_ksum)
// w=2 -> v: plain                        -> g_v
// 128x128 block tile, K-tile 16, 8x8 per thread, 256 threads.
// ---------------------------------------------------------------------------
#define TM 128
#define TN 128
#define TKK 16

__global__ __launch_bounds__(256,1) void gemm_qkv_kernel(
    const float* __restrict__ X,
    const float* __restrict__ Wq, const float* __restrict__ bq,
    const float* __restrict__ Wk, const float* __restrict__ bk,
    const float* __restrict__ Wv, const float* __restrict__ bv)
{
    const int w = blockIdx.z;
    const float* W    = (w==0) ? Wq : ((w==1) ? Wk : Wv);
    const float* bias = (w==0) ? bq : ((w==1) ? bk : bv);
    float* OUT        = (w==0) ? g_q : ((w==1) ? g_k : g_v);

    __shared__ float As[TKK][TM+4];
    __shared__ float Bs[TKK][TN+4];

    const int m0 = blockIdx.y * TM;
    const int n0 = blockIdx.x * TN;
    const int tid = threadIdx.x;
    const int tx = tid & 15;   // column direction
    const int ty = tid >> 4;   // row direction

    float acc[8][8];
    #pragma unroll
    for (int i = 0; i < 8; i++)
        #pragma unroll
        for (int j = 0; j < 8; j++) acc[i][j] = 0.f;

    for (int k0 = 0; k0 < C_; k0 += TKK) {
        #pragma unroll
        for (int l = 0; l < 2; l++) {
            int idx = tid + l*256;       // 0..511
            int row = idx >> 2;          // 0..127
            int c4  = idx & 3;           // 0..3
            float4 a = *(const float4*)(X + (size_t)(m0+row)*C_ + k0 + c4*4);
            As[c4*4+0][row]=a.x; As[c4*4+1][row]=a.y; As[c4*4+2][row]=a.z; As[c4*4+3][row]=a.w;
            float4 b = *(const float4*)(W + (size_t)(n0+row)*C_ + k0 + c4*4);
            Bs[c4*4+0][row]=b.x; Bs[c4*4+1][row]=b.y; Bs[c4*4+2][row]=b.z; Bs[c4*4+3][row]=b.w;
        }
        __syncthreads();
        #pragma unroll
        for (int kk = 0; kk < TKK; kk++) {
            float4 a0 = *(const float4*)&As[kk][ty*8];
            float4 a1 = *(const float4*)&As[kk][ty*8+4];
            float4 b0 = *(const float4*)&Bs[kk][tx*8];
            float4 b1 = *(const float4*)&Bs[kk][tx*8+4];
            float av[8] = {a0.x,a0.y,a0.z,a0.w,a1.x,a1.y,a1.z,a1.w};
            float bv8[8] = {b0.x,b0.y,b0.z,b0.w,b1.x,b1.y,b1.z,b1.w};
            #pragma unroll
            for (int i = 0; i < 8; i++)
                #pragma unroll
                for (int j = 0; j < 8; j++)
                    acc[i][j] = fmaf(av[i], bv8[j], acc[i][j]);
        }
        __syncthreads();
    }

    // Epilogue
    const int b = m0 / N_;               // whole block inside one batch (2048 % 128 == 0)
    float invf[4];
    if (w == 1) {
        #pragma unroll
        for (int jp = 0; jp < 4; jp++) {
            int c = n0 + tx*8 + 2*jp;    // even channel = 2*pair_index
            invf[jp] = expf(-((float)c / 1024.f) * LN10000);
        }
    }
    float chsum[8];
    #pragma unroll
    for (int j = 0; j < 8; j++) chsum[j] = 0.f;

    #pragma unroll
    for (int i = 0; i < 8; i++) {
        int m = m0 + ty*8 + i;
        int n = m - b*N_;
        #pragma unroll
        for (int j = 0; j < 8; j += 2) {
            int c = n0 + tx*8 + j;
            float v0 = acc[i][j]   + bias[c];
            float v1 = acc[i][j+1] + bias[c+1];
            if (w < 2) {
                v0 = gelu_exact(v0) + 0.21f;
                v1 = gelu_exact(v1) + 0.21f;
            }
            if (w == 1) {
                chsum[j]   += v0;
                chsum[j+1] += v1;
                float s, co;
                sincosf((float)n * invf[j>>1], &s, &co);
                float r0 = v0*co - v1*s;
                float r1 = v1*co + v0*s;
                v0 = r0; v1 = r1;
            }
            float2 o; o.x = v0; o.y = v1;
            *(float2*)(OUT + (size_t)m*C_ + c) = o;
        }
    }
    if (w == 1) {
        #pragma unroll
        for (int j = 0; j < 8; j++)
            atomicAdd(&g_ksum[b*C_ + n0 + tx*8 + j], chsum[j]);
    }
}

// ---------------------------------------------------------------------------
// kv[bh][d][e] = (1/N) * sum_n k_rope[n,d] * v[n,e]   (d,e = 64x64 per head)
// one block per (b,h); 256 threads, 4x4 per-thread tile over 64x64.
// ---------------------------------------------------------------------------
__global__ __launch_bounds__(256,1) void kv_kernel()
{
    const int bh = blockIdx.x;
    const int b = bh >> 4, h = bh & 15;
    __shared__ float ks[64][68];
    __shared__ float vs[64][68];

    const int tid = threadIdx.x;
    const int te = tid & 15, td = tid >> 4;

    float acc[4][4];
    #pragma unroll
    for (int i = 0; i < 4; i++)
        #pragma unroll
        for (int j = 0; j < 4; j++) acc[i][j] = 0.f;

    const float* kbase = g_k + (size_t)b*N_*C_ + h*D_;
    const float* vbase = g_v + (size_t)b*N_*C_ + h*D_;

    for (int nt = 0; nt < N_; nt += 64) {
        #pragma unroll
        for (int l = 0; l < 4; l++) {
            int idx = tid + l*256;     // 0..1023
            int row = idx >> 4;        // 0..63
            int c4  = idx & 15;        // 0..15
            *(float4*)&ks[row][c4*4] = *(const float4*)(kbase + (size_t)(nt+row)*C_ + c4*4);
            *(float4*)&vs[row][c4*4] = *(const float4*)(vbase + (size_t)(nt+row)*C_ + c4*4);
        }
        __syncthreads();
        #pragma unroll 8
        for (int nn = 0; nn < 64; nn++) {
            float4 kd = *(const float4*)&ks[nn][td*4];
            float4 ve = *(const float4*)&vs[nn][te*4];
            float kv4[4] = {kd.x, kd.y, kd.z, kd.w};
            float vv4[4] = {ve.x, ve.y, ve.z, ve.w};
            #pragma unroll
            for (int i = 0; i < 4; i++)
                #pragma unroll
                for (int j = 0; j < 4; j++)
                    acc[i][j] = fmaf(kv4[i], vv4[j], acc[i][j]);
        }
        __syncthreads();
    }

    const float sc = 1.f / (float)N_;
    float* kvout = g_kv + ((size_t)bh*D_ + td*4)*D_ + te*4;
    #pragma unroll
    for (int i = 0; i < 4; i++) {
        float4 o;
        o.x = acc[i][0]*sc; o.y = acc[i][1]*sc; o.z = acc[i][2]*sc; o.w = acc[i][3]*sc;
        *(float4*)(kvout + i*D_) = o;
    }
}

// ---------------------------------------------------------------------------
// out_attn[b,n,h*64+e] = z[n] * sum_d rope(q)[n,d] * kv[d,e]
// z[n] = 1/(dot(q_pre_rope[n,:], kmean) + 1e-6)
// grid: (N/64, B*H); 256 threads; thread = (row = tid>>2, quarter = tid&3).
// ---------------------------------------------------------------------------
__global__ __launch_bounds__(256,1) void zout_kernel()
{
    const int bh = blockIdx.y;
    const int b = bh >> 4, h = bh & 15;
    const int n0 = blockIdx.x * 64;

    __shared__ float qs[64][68];
    __shared__ float kvs[64][68];
    __shared__ float kms[64];
    __shared__ float zsh[64];

    const int tid = threadIdx.x;
    const int row = tid >> 2;
    const int qtr = tid & 3;

    if (tid < 64) kms[tid] = g_ksum[b*C_ + h*D_ + tid] * (1.f / (float)N_);
    __syncthreads();

    const int n = n0 + row;
    const float* qrow = g_q + ((size_t)(b*N_ + n))*C_ + h*D_;
    float zp = 0.f;
    #pragma unroll
    for (int l = 0; l < 4; l++) {
        int cl = qtr*16 + l*4;
        float4 qv = *(const float4*)(qrow + cl);
        zp += qv.x*kms[cl] + qv.y*kms[cl+1] + qv.z*kms[cl+2] + qv.w*kms[cl+3];
        int cg = h*D_ + cl;   // even channel -> 2*pair_index
        float invf0 = expf(-((float)cg       / 1024.f) * LN10000);
        float invf1 = expf(-((float)(cg + 2) / 1024.f) * LN10000);
        float s0, c0, s1, c1;
        sincosf((float)n * invf0, &s0, &c0);
        sincosf((float)n * invf1, &s1, &c1);
        float4 r;
        r.x = qv.x*c0 - qv.y*s0;
        r.y = qv.y*c0 + qv.x*s0;
        r.z = qv.z*c1 - qv.w*s1;
        r.w = qv.w*c1 + qv.z*s1;
        *(float4*)&qs[row][cl] = r;
    }
    // kv tile
    #pragma unroll
    for (int l = 0; l < 4; l++) {
        int idx = tid + l*256;
        int rd = idx >> 4;
        int c4 = idx & 15;
        *(float4*)&kvs[rd][c4*4] = *(const float4*)(g_kv + (size_t)bh*D_*D_ + rd*D_ + c4*4);
    }
    // reduce z across the 4 lanes of this row
    zp += __shfl_xor_sync(0xffffffffu, zp, 1);
    zp += __shfl_xor_sync(0xffffffffu, zp, 2);
    if (qtr == 0) zsh[row] = 1.f / (zp + 1e-6f);
    __syncthreads();

    float acc[16];
    #pragma unroll
    for (int e = 0; e < 16; e++) acc[e] = 0.f;
    #pragma unroll 8
    for (int d = 0; d < 64; d++) {
        float qv = qs[row][d];
        #pragma unroll
        for (int l = 0; l < 4; l++) {
            float4 k4 = *(const float4*)&kvs[d][qtr*16 + l*4];
            acc[l*4+0] = fmaf(qv, k4.x, acc[l*4+0]);
            acc[l*4+1] = fmaf(qv, k4.y, acc[l*4+1]);
            acc[l*4+2] = fmaf(qv, k4.z, acc[l*4+2]);
            acc[l*4+3] = fmaf(qv, k4.w, acc[l*4+3]);
        }
    }
    const float z = zsh[row];
    float* o = g_attn + ((size_t)(b*N_ + n))*C_ + h*D_ + qtr*16;
    #pragma unroll
    for (int l = 0; l < 4; l++) {
        float4 r;
        r.x = acc[l*4+0]*z; r.y = acc[l*4+1]*z; r.z = acc[l*4+2]*z; r.w = acc[l*4+3]*z;
        *(float4*)(o + l*4) = r;
    }
}

// ---------------------------------------------------------------------------
// LayerNorm(res = attn + x) * gamma + beta ; biased variance, eps 1e-12
// one block per (b,n) row; 256 threads * 4 floats.
// ---------------------------------------------------------------------------
__global__ __launch_bounds__(256,1) void ln_kernel(
    const float* __restrict__ X,
    const float* __restrict__ gamma,
    const float* __restrict__ beta,
    float* __restrict__ out)
{
    const int m = blockIdx.x;
    const int tid = threadIdx.x;
    const float* xr = X + (size_t)m*C_;
    const float* ar = g_attn + (size_t)m*C_;

    float4 xv = *(const float4*)(xr + tid*4);
    float4 av = *(const float4*)(ar + tid*4);
    float4 r;
    r.x = xv.x + av.x; r.y = xv.y + av.y; r.z = xv.z + av.z; r.w = xv.w + av.w;

    float s1 = r.x + r.y + r.z + r.w;
    float s2 = r.x*r.x + r.y*r.y + r.z*r.z + r.w*r.w;
    #pragma unroll
    for (int o = 16; o > 0; o >>= 1) {
        s1 += __shfl_xor_sync(0xffffffffu, s1, o);
        s2 += __shfl_xor_sync(0xffffffffu, s2, o);
    }
    __shared__ float rs1[8], rs2[8], stats[2];
    int wid = tid >> 5, lane = tid & 31;
    if (lane == 0) { rs1[wid] = s1; rs2[wid] = s2; }
    __syncthreads();
    if (tid == 0) {
        float a = 0.f, bsum = 0.f;
        #pragma unroll
        for (int i = 0; i < 8; i++) { a += rs1[i]; bsum += rs2[i]; }
        stats[0] = a; stats[1] = bsum;
    }
    __syncthreads();
    float mean = stats[0] * (1.f / (float)C_);
    float var  = stats[1] * (1.f / (float)C_) - mean*mean;
    float inv  = rsqrtf(var + 1e-12f);

    float4 g4 = *(const float4*)(gamma + tid*4);
    float4 b4 = *(const float4*)(beta + tid*4);
    float4 o;
    o.x = (r.x - mean)*inv*g4.x + b4.x;
    o.y = (r.y - mean)*inv*g4.y + b4.y;
    o.z = (r.z - mean)*inv*g4.z + b4.z;
    o.w = (r.w - mean)*inv*g4.w + b4.w;
    *(float4*)(out + (size_t)m*C_ + tid*4) = o;
}

extern "C" void kernel_launch(void* const* d_in, const int* in_sizes, int n_in,
                              void* d_out, int out_size)
{
    const float* x     = (const float*)d_in[0];
    const float* Wq    = (const float*)d_in[1];
    const float* bq    = (const float*)d_in[2];
    const float* Wk    = (const float*)d_in[3];
    const float* bk    = (const float*)d_in[4];
    const float* Wv    = (const float*)d_in[5];
    const float* bv    = (const float*)d_in[6];
    const float* gamma = (const float*)d_in[7];
    const float* beta  = (const float*)d_in[8];
    float* out = (float*)d_out;

    zero_ksum_kernel<<<32, 256>>>();
    dim3 gg(C_/TN, M_/TM, 3);
    gemm_qkv_kernel<<<gg, 256>>>(x, Wq, bq, Wk, bk, Wv, bv);
    kv_kernel<<<B_*H_, 256>>>();
    dim3 gz(N_/64, B_*H_);
    zout_kernel<<<gz, 256>>>();
    ln_kernel<<<M_, 256>>>(x, gamma, beta, out);
}

// round 4
// speedup vs baseline: 1.8828x; 1.8828x over previous
#include <cuda_runtime.h>
#include <cuda_bf16.h>
#include <math.h>
#include <stdint.h>

#define B_  8
#define N_  2048
#define C_  1024
#define H_  16
#define D_  64
#define M_  (B_*N_)   // 16384
#define LN10000 9.210340371976184f

// ---------------- device scratch (allocation-free contract) ----------------
__device__ float g_q[M_*C_];                 // gelu(q)+0.21, PRE-rope
__device__ float g_k[M_*C_];                 // gelu(k)+0.21, PRE-rope
__device__ float g_v[M_*C_];
__device__ float g_attn[M_*C_];
__device__ float g_ksum[B_*C_];              // sum_n of pre-rope k (no atomics)
__device__ float g_kv[B_*H_*D_*D_];
__device__ float2 g_tab[N_*(C_/2)];          // rope (cos,sin) per (n, pair)
__device__ __nv_bfloat16 g_xhi[M_*C_];
__device__ __nv_bfloat16 g_xlo[M_*C_];
__device__ __nv_bfloat16 g_whi[3][C_*C_];
__device__ __nv_bfloat16 g_wlo[3][C_*C_];

__device__ __forceinline__ float gelu_exact(float x){
    return 0.5f*x*(1.0f+erff(x*0.70710678118654752f));
}
__device__ __forceinline__ uint32_t smem_u32(const void* p){
    uint32_t a;
    asm("{ .reg .u64 t; cvta.to.shared.u64 t, %1; cvt.u32.u64 %0, t; }" : "=r"(a) : "l"(p));
    return a;
}
__device__ __forceinline__ void ldm4(uint32_t* r, uint32_t addr){
    asm volatile("ldmatrix.sync.aligned.m8n8.x4.shared.b16 {%0,%1,%2,%3}, [%4];"
        : "=r"(r[0]),"=r"(r[1]),"=r"(r[2]),"=r"(r[3]) : "r"(addr));
}
__device__ __forceinline__ void mma16816(float* c, const uint32_t* a, const uint32_t* b){
    asm volatile("mma.sync.aligned.m16n8k16.row.col.f32.bf16.bf16.f32 "
        "{%0,%1,%2,%3}, {%4,%5,%6,%7}, {%8,%9}, {%0,%1,%2,%3};"
        : "+f"(c[0]), "+f"(c[1]), "+f"(c[2]), "+f"(c[3])
        : "r"(a[0]), "r"(a[1]), "r"(a[2]), "r"(a[3]), "r"(b[0]), "r"(b[1]));
}

// ---------------- rope table ----------------
__global__ void rope_table_kernel(){
    int idx = blockIdx.x*256 + threadIdx.x;      // n*512 + p
    int n = idx >> 9;
    int p = idx & 511;
    float invf = expf(-((float)(2*p) / 1024.f) * LN10000);
    float s, c;
    sincosf((float)n * invf, &s, &c);
    g_tab[idx] = make_float2(c, s);
}

// ---------------- fp32 -> bf16 hi/lo split ----------------
__global__ void conv_x_kernel(const float* __restrict__ X){
    size_t i = ((size_t)blockIdx.x*256 + threadIdx.x)*4;
    float4 v = *(const float4*)(X + i);
    __nv_bfloat16 h0 = __float2bfloat16(v.x), h1 = __float2bfloat16(v.y);
    __nv_bfloat16 h2 = __float2bfloat16(v.z), h3 = __float2bfloat16(v.w);
    __nv_bfloat16 l0 = __float2bfloat16(v.x - __bfloat162float(h0));
    __nv_bfloat16 l1 = __float2bfloat16(v.y - __bfloat162float(h1));
    __nv_bfloat16 l2 = __float2bfloat16(v.z - __bfloat162float(h2));
    __nv_bfloat16 l3 = __float2bfloat16(v.w - __bfloat162float(h3));
    __nv_bfloat162 ha = __halves2bfloat162(h0,h1), hb = __halves2bfloat162(h2,h3);
    __nv_bfloat162 la = __halves2bfloat162(l0,l1), lb = __halves2bfloat162(l2,l3);
    uint2 hu, lu;
    hu.x = *(uint32_t*)&ha; hu.y = *(uint32_t*)&hb;
    lu.x = *(uint32_t*)&la; lu.y = *(uint32_t*)&lb;
    *(uint2*)(g_xhi + i) = hu;
    *(uint2*)(g_xlo + i) = lu;
}

__global__ void conv_w_kernel(const float* __restrict__ Wq,
                              const float* __restrict__ Wk,
                              const float* __restrict__ Wv){
    const int w = blockIdx.y;
    const float* W = (w==0)? Wq : (w==1)? Wk : Wv;
    size_t i = ((size_t)blockIdx.x*256 + threadIdx.x)*4;
    float4 v = *(const float4*)(W + i);
    __nv_bfloat16 h0 = __float2bfloat16(v.x), h1 = __float2bfloat16(v.y);
    __nv_bfloat16 h2 = __float2bfloat16(v.z), h3 = __float2bfloat16(v.w);
    __nv_bfloat16 l0 = __float2bfloat16(v.x - __bfloat162float(h0));
    __nv_bfloat16 l1 = __float2bfloat16(v.y - __bfloat162float(h1));
    __nv_bfloat16 l2 = __float2bfloat16(v.z - __bfloat162float(h2));
    __nv_bfloat16 l3 = __float2bfloat16(v.w - __bfloat162float(h3));
    __nv_bfloat162 ha = __halves2bfloat162(h0,h1), hb = __halves2bfloat162(h2,h3);
    __nv_bfloat162 la = __halves2bfloat162(l0,l1), lb = __halves2bfloat162(l2,l3);
    uint2 hu, lu;
    hu.x = *(uint32_t*)&ha; hu.y = *(uint32_t*)&hb;
    lu.x = *(uint32_t*)&la; lu.y = *(uint32_t*)&lb;
    *(uint2*)(g_whi[w] + i) = hu;
    *(uint2*)(g_wlo[w] + i) = lu;
}

// ---------------------------------------------------------------------------
// mma.sync bf16 GEMM: OUT[m,c] = epi( sum over concat-K of A'[m,:] . B'[c,:] )
// A' = [xhi | xhi | xlo] (K=3072), B' = [whi | wlo | whi]
// Tiles: 128x128x32, 4-stage cp.async, 8 warps (4m x 2n), warp tile 32x64.
// ---------------------------------------------------------------------------
#define BM 128
#define BN 128
#define BK 32
#define ASTRIDE 80                      // smem bytes per 32-bf16 row (padded)
#define TILE_BYTES (BM*ASTRIDE)         // 10240
#define STAGE_BYTES (2*TILE_BYTES)      // A + B
#define SMEM_TOT (4*STAGE_BYTES)        // 81920
#define NCHUNK 96

__device__ __forceinline__ void stage_load(uint32_t sa, uint32_t sbB, int chunk,
                                           int w, int m0, int n0, int tid){
    const int pass = chunk >> 5;
    const int kk = (chunk & 31) << 5;   // bf16 element offset in [0,1024)
    const __nv_bfloat16* Asrc = (pass < 2) ? g_xhi : g_xlo;
    const __nv_bfloat16* Bsrc = (pass == 1) ? g_wlo[w] : g_whi[w];
    #pragma unroll
    for (int r = 0; r < 2; r++){
        int cid = tid + r*256;
        int row = cid >> 2, ch = cid & 3;
        uint64_t ga = (uint64_t)__cvta_generic_to_global(
            (const void*)(Asrc + (size_t)(m0+row)*C_ + kk + ch*8));
        asm volatile("cp.async.cg.shared.global [%0], [%1], 16;"
                     :: "r"(sa + row*ASTRIDE + ch*16), "l"(ga));
        uint64_t gb = (uint64_t)__cvta_generic_to_global(
            (const void*)(Bsrc + (size_t)(n0+row)*C_ + kk + ch*8));
        asm volatile("cp.async.cg.shared.global [%0], [%1], 16;"
                     :: "r"(sbB + row*ASTRIDE + ch*16), "l"(gb));
    }
}

__global__ void __launch_bounds__(256) mma_gemm_kernel(
    const float* __restrict__ bq, const float* __restrict__ bk, const float* __restrict__ bv)
{
    extern __shared__ char smem[];
    const int tid  = threadIdx.x;
    const int lane = tid & 31;
    const int wid  = tid >> 5;
    const int wm   = wid & 3;       // 0..3 -> m offset *32
    const int wn   = wid >> 2;      // 0..1 -> n offset *64
    const int w  = blockIdx.z;
    const int n0 = blockIdx.x * BN;
    const int m0 = blockIdx.y * BM;
    const uint32_t sb = smem_u32(smem);

    float acc[2][8][4];
    #pragma unroll
    for (int a = 0; a < 2; a++)
        #pragma unroll
        for (int bb = 0; bb < 8; bb++)
            #pragma unroll
            for (int cdx = 0; cdx < 4; cdx++) acc[a][bb][cdx] = 0.f;

    // prologue: stages 0..2
    #pragma unroll
    for (int s = 0; s < 3; s++){
        stage_load(sb + s*STAGE_BYTES, sb + s*STAGE_BYTES + TILE_BYTES, s, w, m0, n0, tid);
        asm volatile("cp.async.commit_group;" ::: "memory");
    }

    // precomputed intra-warp ldmatrix address offsets
    const uint32_t a_off = (uint32_t)((wm*32 + (lane & 15))*ASTRIDE + ((lane >> 4) << 3)*2);
    const uint32_t b_off = (uint32_t)((wn*64 + (lane & 7) + ((lane >> 4) << 3))*ASTRIDE
                                      + (((lane >> 3) & 1) << 3)*2);

    for (int i = 0; i < NCHUNK; i++){
        if (i < NCHUNK-2)        asm volatile("cp.async.wait_group 2;" ::: "memory");
        else if (i == NCHUNK-2)  asm volatile("cp.async.wait_group 1;" ::: "memory");
        else                     asm volatile("cp.async.wait_group 0;" ::: "memory");
        __syncthreads();

        if (i + 3 < NCHUNK){
            int s = (i+3) & 3;
            stage_load(sb + s*STAGE_BYTES, sb + s*STAGE_BYTES + TILE_BYTES, i+3, w, m0, n0, tid);
            asm volatile("cp.async.commit_group;" ::: "memory");
        }

        const uint32_t abase = sb + (i & 3)*STAGE_BYTES;
        const uint32_t bbase = abase + TILE_BYTES;
        #pragma unroll
        for (int ks = 0; ks < 2; ks++){
            uint32_t af[2][4];
            #pragma unroll
            for (int fm = 0; fm < 2; fm++)
                ldm4(af[fm], abase + a_off + fm*16*ASTRIDE + ks*32);
            #pragma unroll
            for (int fn2 = 0; fn2 < 4; fn2++){
                uint32_t bf[4];
                ldm4(bf, bbase + b_off + fn2*16*ASTRIDE + ks*32);
                #pragma unroll
                for (int fm = 0; fm < 2; fm++){
                    mma16816(acc[fm][fn2*2],   af[fm], bf);
                    mma16816(acc[fm][fn2*2+1], af[fm], bf+2);
                }
            }
        }
    }

    // epilogue: bias + (gelu+0.21 for q,k)
    const float* bias = (w==0)? bq : (w==1)? bk : bv;
    float* OUT = (w==0)? g_q : (w==1)? g_k : g_v;
    #pragma unroll
    for (int fm = 0; fm < 2; fm++){
        const int row0 = m0 + wm*32 + fm*16 + (lane >> 2);
        #pragma unroll
        for (int fn = 0; fn < 8; fn++){
            const int col = n0 + wn*64 + fn*8 + (lane & 3)*2;
            const float b0 = bias[col], b1 = bias[col+1];
            float v0 = acc[fm][fn][0] + b0;
            float v1 = acc[fm][fn][1] + b1;
            float v2 = acc[fm][fn][2] + b0;
            float v3 = acc[fm][fn][3] + b1;
            if (w < 2){
                v0 = gelu_exact(v0) + 0.21f;
                v1 = gelu_exact(v1) + 0.21f;
                v2 = gelu_exact(v2) + 0.21f;
                v3 = gelu_exact(v3) + 0.21f;
            }
            float2 o01; o01.x = v0; o01.y = v1;
            float2 o23; o23.x = v2; o23.y = v3;
            *(float2*)(OUT + (size_t)row0*C_ + col)     = o01;
            *(float2*)(OUT + (size_t)(row0+8)*C_ + col) = o23;
        }
    }
}

// ---------------------------------------------------------------------------
// kv[bh][d][e] = (1/N) sum_n rope(k)[n,d] * v[n,e]; also ksum (no atomics)
// ---------------------------------------------------------------------------
__global__ __launch_bounds__(256,1) void kv_kernel()
{
    const int bh = blockIdx.x;
    const int b = bh >> 4, h = bh & 15;
    __shared__ float ks[64][68];
    __shared__ float vs[64][68];
    __shared__ float cs[16][68];

    const int tid = threadIdx.x;
    const int te = tid & 15, td = tid >> 4;
    const int c4 = tid & 15;
    const int p0 = (h*D_ + c4*4) >> 1;

    float acc[4][4];
    #pragma unroll
    for (int i = 0; i < 4; i++)
        #pragma unroll
        for (int j = 0; j < 4; j++) acc[i][j] = 0.f;
    float csum[4] = {0.f,0.f,0.f,0.f};

    const float* kbase = g_k + (size_t)b*N_*C_ + h*D_;
    const float* vbase = g_v + (size_t)b*N_*C_ + h*D_;

    for (int nt = 0; nt < N_; nt += 64) {
        #pragma unroll
        for (int l = 0; l < 4; l++) {
            int row = (tid >> 4) + l*16;
            int n = nt + row;
            float4 kk = *(const float4*)(kbase + (size_t)n*C_ + c4*4);
            csum[0] += kk.x; csum[1] += kk.y; csum[2] += kk.z; csum[3] += kk.w;
            float2 t0 = g_tab[n*(C_/2) + p0];
            float2 t1 = g_tab[n*(C_/2) + p0 + 1];
            float4 r;
            r.x = kk.x*t0.x - kk.y*t0.y;
            r.y = kk.y*t0.x + kk.x*t0.y;
            r.z = kk.z*t1.x - kk.w*t1.y;
            r.w = kk.w*t1.x + kk.z*t1.y;
            *(float4*)&ks[row][c4*4] = r;
            *(float4*)&vs[row][c4*4] = *(const float4*)(vbase + (size_t)n*C_ + c4*4);
        }
        __syncthreads();
        #pragma unroll 8
        for (int nn = 0; nn < 64; nn++) {
            float4 kd = *(const float4*)&ks[nn][td*4];
            float4 ve = *(const float4*)&vs[nn][te*4];
            float kv4[4] = {kd.x, kd.y, kd.z, kd.w};
            float vv4[4] = {ve.x, ve.y, ve.z, ve.w};
            #pragma unroll
            for (int i = 0; i < 4; i++)
                #pragma unroll
                for (int j = 0; j < 4; j++)
                    acc[i][j] = fmaf(kv4[i], vv4[j], acc[i][j]);
        }
        __syncthreads();
    }

    *(float4*)&cs[tid>>4][c4*4] = make_float4(csum[0], csum[1], csum[2], csum[3]);
    __syncthreads();
    if (tid < 64) {
        float s = 0.f;
        #pragma unroll
        for (int r2 = 0; r2 < 16; r2++) s += cs[r2][tid];
        g_ksum[b*C_ + h*D_ + tid] = s;
    }

    const float sc = 1.f / (float)N_;
    float* kvout = g_kv + ((size_t)bh*D_ + td*4)*D_ + te*4;
    #pragma unroll
    for (int i = 0; i < 4; i++) {
        float4 o;
        o.x = acc[i][0]*sc; o.y = acc[i][1]*sc; o.z = acc[i][2]*sc; o.w = acc[i][3]*sc;
        *(float4*)(kvout + i*D_) = o;
    }
}

// ---------------------------------------------------------------------------
// out_attn = z * (rope(q) @ kv); z = 1/(dot(q_pre, kmean)+1e-6). Table rope.
// ---------------------------------------------------------------------------
__global__ __launch_bounds__(256,1) void zout_kernel()
{
    const int bh = blockIdx.y;
    const int b = bh >> 4, h = bh & 15;
    const int n0 = blockIdx.x * 64;

    __shared__ float qs[64][68];
    __shared__ float kvs[64][68];
    __shared__ float kms[64];
    __shared__ float zsh[64];

    const int tid = threadIdx.x;
    const int row = tid >> 2;
    const int qtr = tid & 3;

    if (tid < 64) kms[tid] = g_ksum[b*C_ + h*D_ + tid] * (1.f / (float)N_);
    __syncthreads();

    const int n = n0 + row;
    const float* qrow = g_q + ((size_t)(b*N_ + n))*C_ + h*D_;
    const int pbase = (h*D_ + qtr*16) >> 1;
    float zp = 0.f;
    #pragma unroll
    for (int l = 0; l < 4; l++) {
        int cl = qtr*16 + l*4;
        float4 qv = *(const float4*)(qrow + cl);
        zp += qv.x*kms[cl] + qv.y*kms[cl+1] + qv.z*kms[cl+2] + qv.w*kms[cl+3];
        float2 t0 = g_tab[n*(C_/2) + pbase + l*2];
        float2 t1 = g_tab[n*(C_/2) + pbase + l*2 + 1];
        float4 r;
        r.x = qv.x*t0.x - qv.y*t0.y;
        r.y = qv.y*t0.x + qv.x*t0.y;
        r.z = qv.z*t1.x - qv.w*t1.y;
        r.w = qv.w*t1.x + qv.z*t1.y;
        *(float4*)&qs[row][cl] = r;
    }
    #pragma unroll
    for (int l = 0; l < 4; l++) {
        int idx = tid + l*256;
        int rd = idx >> 4;
        int cc4 = idx & 15;
        *(float4*)&kvs[rd][cc4*4] = *(const float4*)(g_kv + (size_t)bh*D_*D_ + rd*D_ + cc4*4);
    }
    zp += __shfl_xor_sync(0xffffffffu, zp, 1);
    zp += __shfl_xor_sync(0xffffffffu, zp, 2);
    if (qtr == 0) zsh[row] = 1.f / (zp + 1e-6f);
    __syncthreads();

    float acc[16];
    #pragma unroll
    for (int e = 0; e < 16; e++) acc[e] = 0.f;
    #pragma unroll 8
    for (int d = 0; d < 64; d++) {
        float qv = qs[row][d];
        #pragma unroll
        for (int l = 0; l < 4; l++) {
            float4 k4 = *(const float4*)&kvs[d][qtr*16 + l*4];
            acc[l*4+0] = fmaf(qv, k4.x, acc[l*4+0]);
            acc[l*4+1] = fmaf(qv, k4.y, acc[l*4+1]);
            acc[l*4+2] = fmaf(qv, k4.z, acc[l*4+2]);
            acc[l*4+3] = fmaf(qv, k4.w, acc[l*4+3]);
        }
    }
    const float z = zsh[row];
    float* o = g_attn + ((size_t)(b*N_ + n))*C_ + h*D_ + qtr*16;
    #pragma unroll
    for (int l = 0; l < 4; l++) {
        float4 r;
        r.x = acc[l*4+0]*z; r.y = acc[l*4+1]*z; r.z = acc[l*4+2]*z; r.w = acc[l*4+3]*z;
        *(float4*)(o + l*4) = r;
    }
}

// ---------------------------------------------------------------------------
// residual + LayerNorm
// ---------------------------------------------------------------------------
__global__ __launch_bounds__(256,1) void ln_kernel(
    const float* __restrict__ X,
    const float* __restrict__ gamma,
    const float* __restrict__ beta,
    float* __restrict__ out)
{
    const int m = blockIdx.x;
    const int tid = threadIdx.x;
    const float* xr = X + (size_t)m*C_;
    const float* ar = g_attn + (size_t)m*C_;

    float4 xv = *(const float4*)(xr + tid*4);
    float4 av = *(const float4*)(ar + tid*4);
    float4 r;
    r.x = xv.x + av.x; r.y = xv.y + av.y; r.z = xv.z + av.z; r.w = xv.w + av.w;

    float s1 = r.x + r.y + r.z + r.w;
    float s2 = r.x*r.x + r.y*r.y + r.z*r.z + r.w*r.w;
    #pragma unroll
    for (int o = 16; o > 0; o >>= 1) {
        s1 += __shfl_xor_sync(0xffffffffu, s1, o);
        s2 += __shfl_xor_sync(0xffffffffu, s2, o);
    }
    __shared__ float rs1[8], rs2[8], stats[2];
    int wid = tid >> 5, lane = tid & 31;
    if (lane == 0) { rs1[wid] = s1; rs2[wid] = s2; }
    __syncthreads();
    if (tid == 0) {
        float a = 0.f, bsum = 0.f;
        #pragma unroll
        for (int i = 0; i < 8; i++) { a += rs1[i]; bsum += rs2[i]; }
        stats[0] = a; stats[1] = bsum;
    }
    __syncthreads();
    float mean = stats[0] * (1.f / (float)C_);
    float var  = stats[1] * (1.f / (float)C_) - mean*mean;
    float inv  = rsqrtf(var + 1e-12f);

    float4 g4 = *(const float4*)(gamma + tid*4);
    float4 b4 = *(const float4*)(beta + tid*4);
    float4 o;
    o.x = (r.x - mean)*inv*g4.x + b4.x;
    o.y = (r.y - mean)*inv*g4.y + b4.y;
    o.z = (r.z - mean)*inv*g4.z + b4.z;
    o.w = (r.w - mean)*inv*g4.w + b4.w;
    *(float4*)(out + (size_t)m*C_ + tid*4) = o;
}

extern "C" void kernel_launch(void* const* d_in, const int* in_sizes, int n_in,
                              void* d_out, int out_size)
{
    const float* x     = (const float*)d_in[0];
    const float* Wq    = (const float*)d_in[1];
    const float* bq    = (const float*)d_in[2];
    const float* Wk    = (const float*)d_in[3];
    const float* bk    = (const float*)d_in[4];
    const float* Wv    = (const float*)d_in[5];
    const float* bv    = (const float*)d_in[6];
    const float* gamma = (const float*)d_in[7];
    const float* beta  = (const float*)d_in[8];
    float* out = (float*)d_out;

    cudaFuncSetAttribute(mma_gemm_kernel, cudaFuncAttributeMaxDynamicSharedMemorySize, SMEM_TOT);

    rope_table_kernel<<<(N_*(C_/2))/256, 256>>>();
    conv_x_kernel<<<(M_*C_)/1024, 256>>>(x);
    conv_w_kernel<<<dim3((C_*C_)/1024, 3), 256>>>(Wq, Wk, Wv);
    mma_gemm_kernel<<<dim3(C_/BN, M_/BM, 3), 256, SMEM_TOT>>>(bq, bk, bv);
    kv_kernel<<<B_*H_, 256>>>();
    zout_kernel<<<dim3(N_/64, B_*H_), 256>>>();
    ln_kernel<<<M_, 256>>>(x, gamma, beta, out);
}

// round 7
// speedup vs baseline: 2.1248x; 1.1285x over previous
#include <cuda_runtime.h>
#include <cuda_bf16.h>
#include <math.h>
#include <stdint.h>

#define B_  8
#define N_  2048
#define C_  1024
#define H_  16
#define D_  64
#define M_  (B_*N_)   // 16384
#define LN10000 9.210340371976184f
#define NKPART 8

// ---------------- device scratch (allocation-free contract) ----------------
__device__ float g_q[M_*C_];                 // gelu(q)+0.21, PRE-rope
__device__ float g_k[M_*C_];                 // gelu(k)+0.21, PRE-rope
__device__ float g_v[M_*C_];
__device__ float g_attn[M_*C_];
__device__ float g_ksum[B_*C_];
__device__ float g_kv[B_*H_*D_*D_];
__device__ float g_kvp[NKPART][B_*H_*D_*D_];
__device__ float g_ksump[NKPART][B_*C_];
__device__ float2 g_tab[N_*(C_/2)];          // rope (cos,sin) per (n, pair)
__device__ __nv_bfloat16 g_xhi[M_*C_];
__device__ __nv_bfloat16 g_xlo[M_*C_];
__device__ __nv_bfloat16 g_whi[3][C_*C_];
__device__ __nv_bfloat16 g_wlo[3][C_*C_];

__device__ __forceinline__ float gelu_exact(float x){
    return 0.5f*x*(1.0f+erff(x*0.70710678118654752f));
}
__device__ __forceinline__ uint32_t smem_u32(const void* p){
    uint32_t a;
    asm("{ .reg .u64 t; cvta.to.shared.u64 t, %1; cvt.u32.u64 %0, t; }" : "=r"(a) : "l"(p));
    return a;
}
__device__ __forceinline__ void ldm4(uint32_t* r, uint32_t addr){
    asm volatile("ldmatrix.sync.aligned.m8n8.x4.shared.b16 {%0,%1,%2,%3}, [%4];"
        : "=r"(r[0]),"=r"(r[1]),"=r"(r[2]),"=r"(r[3]) : "r"(addr));
}
__device__ __forceinline__ void mma16816(float* c, const uint32_t* a, const uint32_t* b){
    asm volatile("mma.sync.aligned.m16n8k16.row.col.f32.bf16.bf16.f32 "
        "{%0,%1,%2,%3}, {%4,%5,%6,%7}, {%8,%9}, {%0,%1,%2,%3};"
        : "+f"(c[0]), "+f"(c[1]), "+f"(c[2]), "+f"(c[3])
        : "r"(a[0]), "r"(a[1]), "r"(a[2]), "r"(a[3]), "r"(b[0]), "r"(b[1]));
}

// ---------------- rope table ----------------
__global__ void rope_table_kernel(){
    int idx = blockIdx.x*256 + threadIdx.x;      // n*512 + p
    int n = idx >> 9;
    int p = idx & 511;
    float invf = expf(-((float)(2*p) / 1024.f) * LN10000);
    float s, c;
    sincosf((float)n * invf, &s, &c);
    g_tab[idx] = make_float2(c, s);
}

// ---------------- fp32 -> bf16 hi/lo split ----------------
__global__ void conv_x_kernel(const float* __restrict__ X){
    size_t i = ((size_t)blockIdx.x*256 + threadIdx.x)*4;
    float4 v = *(const float4*)(X + i);
    __nv_bfloat16 h0 = __float2bfloat16(v.x), h1 = __float2bfloat16(v.y);
    __nv_bfloat16 h2 = __float2bfloat16(v.z), h3 = __float2bfloat16(v.w);
    __nv_bfloat16 l0 = __float2bfloat16(v.x - __bfloat162float(h0));
    __nv_bfloat16 l1 = __float2bfloat16(v.y - __bfloat162float(h1));
    __nv_bfloat16 l2 = __float2bfloat16(v.z - __bfloat162float(h2));
    __nv_bfloat16 l3 = __float2bfloat16(v.w - __bfloat162float(h3));
    __nv_bfloat162 ha = __halves2bfloat162(h0,h1), hb = __halves2bfloat162(h2,h3);
    __nv_bfloat162 la = __halves2bfloat162(l0,l1), lb = __halves2bfloat162(l2,l3);
    uint2 hu, lu;
    hu.x = *(uint32_t*)&ha; hu.y = *(uint32_t*)&hb;
    lu.x = *(uint32_t*)&la; lu.y = *(uint32_t*)&lb;
    *(uint2*)(g_xhi + i) = hu;
    *(uint2*)(g_xlo + i) = lu;
}

__global__ void conv_w_kernel(const float* __restrict__ Wq,
                              const float* __restrict__ Wk,
                              const float* __restrict__ Wv){
    const int w = blockIdx.y;
    const float* W = (w==0)? Wq : (w==1)? Wk : Wv;
    size_t i = ((size_t)blockIdx.x*256 + threadIdx.x)*4;
    float4 v = *(const float4*)(W + i);
    __nv_bfloat16 h0 = __float2bfloat16(v.x), h1 = __float2bfloat16(v.y);
    __nv_bfloat16 h2 = __float2bfloat16(v.z), h3 = __float2bfloat16(v.w);
    __nv_bfloat16 l0 = __float2bfloat16(v.x - __bfloat162float(h0));
    __nv_bfloat16 l1 = __float2bfloat16(v.y - __bfloat162float(h1));
    __nv_bfloat16 l2 = __float2bfloat16(v.z - __bfloat162float(h2));
    __nv_bfloat16 l3 = __float2bfloat16(v.w - __bfloat162float(h3));
    __nv_bfloat162 ha = __halves2bfloat162(h0,h1), hb = __halves2bfloat162(h2,h3);
    __nv_bfloat162 la = __halves2bfloat162(l0,l1), lb = __halves2bfloat162(l2,l3);
    uint2 hu, lu;
    hu.x = *(uint32_t*)&ha; hu.y = *(uint32_t*)&hb;
    lu.x = *(uint32_t*)&la; lu.y = *(uint32_t*)&lb;
    *(uint2*)(g_whi[w] + i) = hu;
    *(uint2*)(g_wlo[w] + i) = lu;
}

// ---------------------------------------------------------------------------
// mma.sync bf16 GEMM, concat-K = [xhi|xhi|xlo] . [whi|wlo|whi]
// Tiles: 128x128x64, 3-stage cp.async (prefetch distance 2), 8 warps (4m x 2n).
// ---------------------------------------------------------------------------
#define BM 128
#define BN 128
#define BK 64
#define ASTRIDE 144                     // 128B row + 16B pad (conflict-free ldmatrix)
#define TILE_BYTES (BM*ASTRIDE)         // 18432
#define STAGE_BYTES (2*TILE_BYTES)      // 36864
#define SMEM_TOT (3*STAGE_BYTES)        // 110592
#define NCHUNK 48

__device__ __forceinline__ void stage_load(uint32_t sa, uint32_t sbB, int chunk,
                                           int w, int m0, int n0, int tid){
    const int pass = chunk >> 4;
    const int kk = (chunk & 15) << 6;   // bf16 element offset in [0,1024)
    const __nv_bfloat16* Asrc = (pass < 2) ? g_xhi : g_xlo;
    const __nv_bfloat16* Bsrc = (pass == 1) ? g_wlo[w] : g_whi[w];
    #pragma unroll
    for (int r = 0; r < 4; r++){
        int cid = tid + r*256;          // 0..1023
        int row = cid >> 3, ch = cid & 7;
        uint64_t ga = (uint64_t)__cvta_generic_to_global(
            (const void*)(Asrc + (size_t)(m0+row)*C_ + kk + ch*8));
        asm volatile("cp.async.cg.shared.global [%0], [%1], 16;"
                     :: "r"(sa + row*ASTRIDE + ch*16), "l"(ga));
        uint64_t gb = (uint64_t)__cvta_generic_to_global(
            (const void*)(Bsrc + (size_t)(n0+row)*C_ + kk + ch*8));
        asm volatile("cp.async.cg.shared.global [%0], [%1], 16;"
                     :: "r"(sbB + row*ASTRIDE + ch*16), "l"(gb));
    }
}

__global__ void __launch_bounds__(256,2) mma_gemm_kernel(
    const float* __restrict__ bq, const float* __restrict__ bk, const float* __restrict__ bv)
{
    extern __shared__ char smem[];
    const int tid  = threadIdx.x;
    const int lane = tid & 31;
    const int wid  = tid >> 5;
    const int wm   = wid & 3;       // m offset *32
    const int wn   = wid >> 2;      // n offset *64
    const int w  = blockIdx.z;
    const int n0 = blockIdx.x * BN;
    const int m0 = blockIdx.y * BM;
    const uint32_t sb = smem_u32(smem);

    float acc[2][8][4];
    #pragma unroll
    for (int a = 0; a < 2; a++)
        #pragma unroll
        for (int bb = 0; bb < 8; bb++)
            #pragma unroll
            for (int cdx = 0; cdx < 4; cdx++) acc[a][bb][cdx] = 0.f;

    // prologue: stages 0,1
    #pragma unroll
    for (int s = 0; s < 2; s++){
        stage_load(sb + s*STAGE_BYTES, sb + s*STAGE_BYTES + TILE_BYTES, s, w, m0, n0, tid);
        asm volatile("cp.async.commit_group;" ::: "memory");
    }

    const uint32_t a_off = (uint32_t)((wm*32 + (lane & 15))*ASTRIDE + ((lane >> 4) << 3)*2);
    const uint32_t b_off = (uint32_t)((wn*64 + (lane & 7) + ((lane >> 4) << 3))*ASTRIDE
                                      + (((lane >> 3) & 1) << 3)*2);

    int bufc = 0;   // buffer of stage i
    for (int i = 0; i < NCHUNK; i++){
        if (i < NCHUNK-1) asm volatile("cp.async.wait_group 1;" ::: "memory");
        else              asm volatile("cp.async.wait_group 0;" ::: "memory");
        __syncthreads();

        if (i + 2 < NCHUNK){
            int bn = bufc + 2; if (bn >= 3) bn -= 3;
            stage_load(sb + bn*STAGE_BYTES, sb + bn*STAGE_BYTES + TILE_BYTES,
                       i+2, w, m0, n0, tid);
            asm volatile("cp.async.commit_group;" ::: "memory");
        }

        const uint32_t abase = sb + bufc*STAGE_BYTES;
        const uint32_t bbase = abase + TILE_BYTES;
        #pragma unroll
        for (int ks = 0; ks < 4; ks++){
            uint32_t af[2][4];
            #pragma unroll
            for (int fm = 0; fm < 2; fm++)
                ldm4(af[fm], abase + a_off + fm*16*ASTRIDE + ks*32);
            #pragma unroll
            for (int fn2 = 0; fn2 < 4; fn2++){
                uint32_t bf[4];
                ldm4(bf, bbase + b_off + fn2*16*ASTRIDE + ks*32);
                #pragma unroll
                for (int fm = 0; fm < 2; fm++){
                    mma16816(acc[fm][fn2*2],   af[fm], bf);
                    mma16816(acc[fm][fn2*2+1], af[fm], bf+2);
                }
            }
        }
        if (++bufc == 3) bufc = 0;
    }

    // epilogue: bias + (gelu+0.21 for q,k)
    const float* bias = (w==0)? bq : (w==1)? bk : bv;
    float* OUT = (w==0)? g_q : (w==1)? g_k : g_v;
    #pragma unroll
    for (int fm = 0; fm < 2; fm++){
        const int row0 = m0 + wm*32 + fm*16 + (lane >> 2);
        #pragma unroll
        for (int fn = 0; fn < 8; fn++){
            const int col = n0 + wn*64 + fn*8 + (lane & 3)*2;
            const float b0 = bias[col], b1 = bias[col+1];
            float v0 = acc[fm][fn][0] + b0;
            float v1 = acc[fm][fn][1] + b1;
            float v2 = acc[fm][fn][2] + b0;
            float v3 = acc[fm][fn][3] + b1;
            if (w < 2){
                v0 = gelu_exact(v0) + 0.21f;
                v1 = gelu_exact(v1) + 0.21f;
                v2 = gelu_exact(v2) + 0.21f;
                v3 = gelu_exact(v3) + 0.21f;
            }
            float2 o01; o01.x = v0; o01.y = v1;
            float2 o23; o23.x = v2; o23.y = v3;
            *(float2*)(OUT + (size_t)row0*C_ + col)     = o01;
            *(float2*)(OUT + (size_t)(row0+8)*C_ + col) = o23;
        }
    }
}

// ---------------------------------------------------------------------------
// kv partials: part p covers rows [p*256, p*256+256).
// g_kvp[p][bh] += rope(k) x v (unscaled); g_ksump[p] = partial pre-rope colsum.
// ---------------------------------------------------------------------------
__global__ __launch_bounds__(256,1) void kv_part_kernel()
{
    const int bh = blockIdx.x;
    const int part = blockIdx.y;
    const int b = bh >> 4, h = bh & 15;
    __shared__ float ks[64][68];
    __shared__ float vs[64][68];
    __shared__ float cs[16][68];

    const int tid = threadIdx.x;
    const int te = tid & 15, td = tid >> 4;
    const int c4 = tid & 15;
    const int p0 = (h*D_ + c4*4) >> 1;

    float acc[4][4];
    #pragma unroll
    for (int i = 0; i < 4; i++)
        #pragma unroll
        for (int j = 0; j < 4; j++) acc[i][j] = 0.f;
    float csum[4] = {0.f,0.f,0.f,0.f};

    const float* kbase = g_k + (size_t)b*N_*C_ + h*D_;
    const float* vbase = g_v + (size_t)b*N_*C_ + h*D_;
    const int nstart = part * (N_/NKPART);

    for (int nt = nstart; nt < nstart + N_/NKPART; nt += 64) {
        #pragma unroll
        for (int l = 0; l < 4; l++) {
            int row = (tid >> 4) + l*16;
            int n = nt + row;
            float4 kk = *(const float4*)(kbase + (size_t)n*C_ + c4*4);
            csum[0] += kk.x; csum[1] += kk.y; csum[2] += kk.z; csum[3] += kk.w;
            float2 t0 = g_tab[n*(C_/2) + p0];
            float2 t1 = g_tab[n*(C_/2) + p0 + 1];
            float4 r;
            r.x = kk.x*t0.x - kk.y*t0.y;
            r.y = kk.y*t0.x + kk.x*t0.y;
            r.z = kk.z*t1.x - kk.w*t1.y;
            r.w = kk.w*t1.x + kk.z*t1.y;
            *(float4*)&ks[row][c4*4] = r;
            *(float4*)&vs[row][c4*4] = *(const float4*)(vbase + (size_t)n*C_ + c4*4);
        }
        __syncthreads();
        #pragma unroll 8
        for (int nn = 0; nn < 64; nn++) {
            float4 kd = *(const float4*)&ks[nn][td*4];
            float4 ve = *(const float4*)&vs[nn][te*4];
            float kv4[4] = {kd.x, kd.y, kd.z, kd.w};
            float vv4[4] = {ve.x, ve.y, ve.z, ve.w};
            #pragma unroll
            for (int i = 0; i < 4; i++)
                #pragma unroll
                for (int j = 0; j < 4; j++)
                    acc[i][j] = fmaf(kv4[i], vv4[j], acc[i][j]);
        }
        __syncthreads();
    }

    *(float4*)&cs[tid>>4][c4*4] = make_float4(csum[0], csum[1], csum[2], csum[3]);
    __syncthreads();
    if (tid < 64) {
        float s = 0.f;
        #pragma unroll
        for (int r2 = 0; r2 < 16; r2++) s += cs[r2][tid];
        g_ksump[part][b*C_ + h*D_ + tid] = s;
    }

    float* kvout = g_kvp[part] + ((size_t)bh*D_ + td*4)*D_ + te*4;
    #pragma unroll
    for (int i = 0; i < 4; i++) {
        float4 o;
        o.x = acc[i][0]; o.y = acc[i][1]; o.z = acc[i][2]; o.w = acc[i][3];
        *(float4*)(kvout + i*D_) = o;
    }
}

__global__ __launch_bounds__(256,1) void kv_reduce_kernel()
{
    const int idx = blockIdx.x*256 + threadIdx.x;   // 0 .. B*H*D*D-1
    float s = 0.f;
    #pragma unroll
    for (int p = 0; p < NKPART; p++) s += g_kvp[p][idx];
    g_kv[idx] = s * (1.f / (float)N_);
    if (idx < B_*C_) {
        float t = 0.f;
        #pragma unroll
        for (int p = 0; p < NKPART; p++) t += g_ksump[p][idx];
        g_ksum[idx] = t;
    }
}

// ---------------------------------------------------------------------------
// out_attn = z * (rope(q) @ kv); z = 1/(dot(q_pre, kmean)+1e-6). Table rope.
// ---------------------------------------------------------------------------
__global__ __launch_bounds__(256,1) void zout_kernel()
{
    const int bh = blockIdx.y;
    const int b = bh >> 4, h = bh & 15;
    const int n0 = blockIdx.x * 64;

    __shared__ float qs[64][68];
    __shared__ float kvs[64][68];
    __shared__ float kms[64];
    __shared__ float zsh[64];

    const int tid = threadIdx.x;
    const int row = tid >> 2;
    const int qtr = tid & 3;

    if (tid < 64) kms[tid] = g_ksum[b*C_ + h*D_ + tid] * (1.f / (float)N_);
    __syncthreads();

    const int n = n0 + row;
    const float* qrow = g_q + ((size_t)(b*N_ + n))*C_ + h*D_;
    const int pbase = (h*D_ + qtr*16) >> 1;
    float zp = 0.f;
    #pragma unroll
    for (int l = 0; l < 4; l++) {
        int cl = qtr*16 + l*4;
        float4 qv = *(const float4*)(qrow + cl);
        zp += qv.x*kms[cl] + qv.y*kms[cl+1] + qv.z*kms[cl+2] + qv.w*kms[cl+3];
        float2 t0 = g_tab[n*(C_/2) + pbase + l*2];
        float2 t1 = g_tab[n*(C_/2) + pbase + l*2 + 1];
        float4 r;
        r.x = qv.x*t0.x - qv.y*t0.y;
        r.y = qv.y*t0.x + qv.x*t0.y;
        r.z = qv.z*t1.x - qv.w*t1.y;
        r.w = qv.w*t1.x + qv.z*t1.y;
        *(float4*)&qs[row][cl] = r;
    }
    #pragma unroll
    for (int l = 0; l < 4; l++) {
        int idx = tid + l*256;
        int rd = idx >> 4;
        int cc4 = idx & 15;
        *(float4*)&kvs[rd][cc4*4] = *(const float4*)(g_kv + (size_t)bh*D_*D_ + rd*D_ + cc4*4);
    }
    zp += __shfl_xor_sync(0xffffffffu, zp, 1);
    zp += __shfl_xor_sync(0xffffffffu, zp, 2);
    if (qtr == 0) zsh[row] = 1.f / (zp + 1e-6f);
    __syncthreads();

    float acc[16];
    #pragma unroll
    for (int e = 0; e < 16; e++) acc[e] = 0.f;
    #pragma unroll 8
    for (int d = 0; d < 64; d++) {
        float qv = qs[row][d];
        #pragma unroll
        for (int l = 0; l < 4; l++) {
            float4 k4 = *(const float4*)&kvs[d][qtr*16 + l*4];
            acc[l*4+0] = fmaf(qv, k4.x, acc[l*4+0]);
            acc[l*4+1] = fmaf(qv, k4.y, acc[l*4+1]);
            acc[l*4+2] = fmaf(qv, k4.z, acc[l*4+2]);
            acc[l*4+3] = fmaf(qv, k4.w, acc[l*4+3]);
        }
    }
    const float z = zsh[row];
    float* o = g_attn + ((size_t)(b*N_ + n))*C_ + h*D_ + qtr*16;
    #pragma unroll
    for (int l = 0; l < 4; l++) {
        float4 r;
        r.x = acc[l*4+0]*z; r.y = acc[l*4+1]*z; r.z = acc[l*4+2]*z; r.w = acc[l*4+3]*z;
        *(float4*)(o + l*4) = r;
    }
}

// ---------------------------------------------------------------------------
// residual + LayerNorm
// ---------------------------------------------------------------------------
__global__ __launch_bounds__(256,1) void ln_kernel(
    const float* __restrict__ X,
    const float* __restrict__ gamma,
    const float* __restrict__ beta,
    float* __restrict__ out)
{
    const int m = blockIdx.x;
    const int tid = threadIdx.x;
    const float* xr = X + (size_t)m*C_;
    const float* ar = g_attn + (size_t)m*C_;

    float4 xv = *(const float4*)(xr + tid*4);
    float4 av = *(const float4*)(ar + tid*4);
    float4 r;
    r.x = xv.x + av.x; r.y = xv.y + av.y; r.z = xv.z + av.z; r.w = xv.w + av.w;

    float s1 = r.x + r.y + r.z + r.w;
    float s2 = r.x*r.x + r.y*r.y + r.z*r.z + r.w*r.w;
    #pragma unroll
    for (int o = 16; o > 0; o >>= 1) {
        s1 += __shfl_xor_sync(0xffffffffu, s1, o);
        s2 += __shfl_xor_sync(0xffffffffu, s2, o);
    }
    __shared__ float rs1[8], rs2[8], stats[2];
    int wid = tid >> 5, lane = tid & 31;
    if (lane == 0) { rs1[wid] = s1; rs2[wid] = s2; }
    __syncthreads();
    if (tid == 0) {
        float a = 0.f, bsum = 0.f;
        #pragma unroll
        for (int i = 0; i < 8; i++) { a += rs1[i]; bsum += rs2[i]; }
        stats[0] = a; stats[1] = bsum;
    }
    __syncthreads();
    float mean = stats[0] * (1.f / (float)C_);
    float var  = stats[1] * (1.f / (float)C_) - mean*mean;
    float inv  = rsqrtf(var + 1e-12f);

    float4 g4 = *(const float4*)(gamma + tid*4);
    float4 b4 = *(const float4*)(beta + tid*4);
    float4 o;
    o.x = (r.x - mean)*inv*g4.x + b4.x;
    o.y = (r.y - mean)*inv*g4.y + b4.y;
    o.z = (r.z - mean)*inv*g4.z + b4.z;
    o.w = (r.w - mean)*inv*g4.w + b4.w;
    *(float4*)(out + (size_t)m*C_ + tid*4) = o;
}

extern "C" void kernel_launch(void* const* d_in, const int* in_sizes, int n_in,
                              void* d_out, int out_size)
{
    const float* x     = (const float*)d_in[0];
    const float* Wq    = (const float*)d_in[1];
    const float* bq    = (const float*)d_in[2];
    const float* Wk    = (const float*)d_in[3];
    const float* bk    = (const float*)d_in[4];
    const float* Wv    = (const float*)d_in[5];
    const float* bv    = (const float*)d_in[6];
    const float* gamma = (const float*)d_in[7];
    const float* beta  = (const float*)d_in[8];
    float* out = (float*)d_out;

    cudaFuncSetAttribute(mma_gemm_kernel, cudaFuncAttributeMaxDynamicSharedMemorySize, SMEM_TOT);

    rope_table_kernel<<<(N_*(C_/2))/256, 256>>>();
    conv_x_kernel<<<(M_*C_)/1024, 256>>>(x);
    conv_w_kernel<<<dim3((C_*C_)/1024, 3), 256>>>(Wq, Wk, Wv);
    mma_gemm_kernel<<<dim3(C_/BN, M_/BM, 3), 256, SMEM_TOT>>>(bq, bk, bv);
    kv_part_kernel<<<dim3(B_*H_, NKPART), 256>>>();
    kv_reduce_kernel<<<(B_*H_*D_*D_)/256, 256>>>();
    zout_kernel<<<dim3(N_/64, B_*H_), 256>>>();
    ln_kernel<<<M_, 256>>>(x, gamma, beta, out);
}